// round 3
// baseline (speedup 1.0000x reference)
#include <cuda_runtime.h>

#define NA 256
#define NU 1024
#define DD 64
#define NE (NA * NU)

// Scratch (static __device__ — no allocation, per harness rules)
__device__ float g_ap_res[(size_t)NE * DD];   // relu(c1[a] + edge.W1b), [a,u,d]
__device__ float g_ue_res[(size_t)NE * DD];   // relu(c2[u] + edge.W2b), [a,u,d]
__device__ float g_ap_sum[NA * DD];
__device__ float g_ue_sum[NU * DD];
__device__ float g_c1[NA * DD];
__device__ float g_c2[NU * DD];

__device__ __forceinline__ float frelu(float x) { return fmaxf(x, 0.0f); }

// ---------------------------------------------------------------------------
// K1: c1[a] = b1 + ap_hid[a] . W1_top ; c2[u] = b2 + ue_hid[u] . W2_top
// grid = NA + NU blocks, 64 threads
// ---------------------------------------------------------------------------
__global__ void k1_pre(const float* __restrict__ ap_hid,
                       const float* __restrict__ ue_hid,
                       const float* __restrict__ W1, const float* __restrict__ b1,
                       const float* __restrict__ W2, const float* __restrict__ b2) {
    __shared__ float sH[DD];
    int bid = blockIdx.x;
    int d = threadIdx.x;  // 0..63
    const float *H, *W, *B;
    float* out;
    if (bid < NA) {
        H = ap_hid + bid * DD; W = W1; B = b1; out = g_c1 + bid * DD;
    } else {
        int u = bid - NA;
        H = ue_hid + u * DD;  W = W2; B = b2; out = g_c2 + u * DD;
    }
    sH[d] = H[d];
    __syncthreads();
    float acc = B[d];
#pragma unroll 8
    for (int k = 0; k < DD; ++k) acc += sH[k] * W[k * DD + d];  // top half rows
    out[d] = acc;
}

// ---------------------------------------------------------------------------
// K2: for 64-edge tile (one a, 64 consecutive u):
//   E[64x64] @ [W1_bot | W2_bot][64x128] -> add c1/c2, relu, store scratch
// 256 threads, BM=64, BN=128, thread tile 8x4. smem = 48KB exactly.
// ---------------------------------------------------------------------------
__global__ void __launch_bounds__(256) k2_gemm1(const float* __restrict__ edge,
                                                const float* __restrict__ W1,
                                                const float* __restrict__ W2) {
    __shared__ float sW[64 * 128];  // sW[k*128 + n]
    __shared__ float sE[64 * 64];   // sE[r*64 + k] (row-major; A-loads are warp-uniform)

    int tid = threadIdx.x;
    int m0 = blockIdx.x * 64;
    int a  = m0 >> 10;
    int u0 = m0 & 1023;

    // Load W bottom halves (rows 64..127 of W1/W2)
#pragma unroll
    for (int i = 0; i < 4; ++i) {
        int lin = tid + i * 256;           // 0..1023
        int k  = lin >> 4;
        int d4 = (lin & 15) * 4;
        float4 w1 = *(const float4*)&W1[(64 + k) * DD + d4];
        float4 w2 = *(const float4*)&W2[(64 + k) * DD + d4];
        *(float4*)&sW[k * 128 + d4]      = w1;
        *(float4*)&sW[k * 128 + 64 + d4] = w2;
    }
    // Load edge tile
#pragma unroll
    for (int i = 0; i < 4; ++i) {
        int lin = tid + i * 256;           // 0..1023
        int r  = lin >> 4;
        int k4 = (lin & 15) * 4;
        *(float4*)&sE[r * 64 + k4] = *(const float4*)&edge[(size_t)(m0 + r) * DD + k4];
    }
    __syncthreads();

    int tr = tid >> 5;  // 0..7  -> rows tr*8 .. tr*8+7
    int tc = tid & 31;  // 0..31 -> cols tc*4 .. tc*4+3 (of 128)

    float acc[8][4];
#pragma unroll
    for (int i = 0; i < 8; ++i)
#pragma unroll
        for (int j = 0; j < 4; ++j) acc[i][j] = 0.0f;

#pragma unroll 4
    for (int k = 0; k < 64; ++k) {
        float4 bv = *(float4*)&sW[k * 128 + tc * 4];
#pragma unroll
        for (int i = 0; i < 8; ++i) {
            float av = sE[(tr * 8 + i) * 64 + k];   // warp-uniform broadcast
            acc[i][0] += av * bv.x;
            acc[i][1] += av * bv.y;
            acc[i][2] += av * bv.z;
            acc[i][3] += av * bv.w;
        }
    }

    if (tc < 16) {
        // ap half: global cols 0..63
        int c = tc * 4;
        float4 cv = *(const float4*)&g_c1[a * DD + c];
#pragma unroll
        for (int i = 0; i < 8; ++i) {
            int m = m0 + tr * 8 + i;
            float4 o;
            o.x = frelu(cv.x + acc[i][0]);
            o.y = frelu(cv.y + acc[i][1]);
            o.z = frelu(cv.z + acc[i][2]);
            o.w = frelu(cv.w + acc[i][3]);
            *(float4*)&g_ap_res[(size_t)m * DD + c] = o;
        }
    } else {
        // ue half: global cols 64..127 -> ue col c
        int c = (tc - 16) * 4;
#pragma unroll
        for (int i = 0; i < 8; ++i) {
            int r = tr * 8 + i;
            int m = m0 + r;
            int u = u0 + r;
            float4 cv = *(const float4*)&g_c2[u * DD + c];
            float4 o;
            o.x = frelu(cv.x + acc[i][0]);
            o.y = frelu(cv.y + acc[i][1]);
            o.z = frelu(cv.z + acc[i][2]);
            o.w = frelu(cv.w + acc[i][3]);
            *(float4*)&g_ue_res[(size_t)m * DD + c] = o;
        }
    }
}

// ---------------------------------------------------------------------------
// K3: ap_sum[a,d] = sum_u ap_res[a,u,d]   (grid = NA, 256 threads)
// ---------------------------------------------------------------------------
__global__ void k3_apsum() {
    int a = blockIdx.x;
    int tid = threadIdx.x;
    int d  = tid & 63;
    int us = tid >> 6;  // 0..3
    const float* base = g_ap_res + (size_t)a * NU * DD;
    float acc = 0.0f;
    for (int u = us; u < NU; u += 4) acc += base[u * DD + d];
    __shared__ float sr[256];
    sr[tid] = acc;
    __syncthreads();
    if (tid < 64)
        g_ap_sum[a * DD + tid] = sr[tid] + sr[tid + 64] + sr[tid + 128] + sr[tid + 192];
}

// ---------------------------------------------------------------------------
// K4: ue_sum[u,d] = sum_a ue_res[a,u,d]   (grid = NU, 256 threads)
// ---------------------------------------------------------------------------
__global__ void k4_uesum() {
    int u = blockIdx.x;
    int tid = threadIdx.x;
    int d  = tid & 63;
    int as = tid >> 6;  // 0..3
    float acc = 0.0f;
    for (int aa = as; aa < NA; aa += 4)
        acc += g_ue_res[((size_t)aa * NU + u) * DD + d];
    __shared__ float sr[256];
    sr[tid] = acc;
    __syncthreads();
    if (tid < 64)
        g_ue_sum[u * DD + tid] = sr[tid] + sr[tid + 64] + sr[tid + 128] + sr[tid + 192];
}

// ---------------------------------------------------------------------------
// K5: out = [edge | agg] @ W3 + b3, agg = ap_sum[a]+ue_sum[u]-ap_res-ue_res
// BM=32 edges (one a), K=128, N=64. 256 threads, thread tile 2x4. smem 48KB.
// ---------------------------------------------------------------------------
__global__ void __launch_bounds__(256) k5_gemm2(const float* __restrict__ edge,
                                                const float* __restrict__ W3,
                                                const float* __restrict__ b3,
                                                float* __restrict__ out) {
    __shared__ float sW3[128 * 64];  // same layout as W3
    __shared__ float sX[32 * 128];   // sX[r*128 + k]: k<64 edge, k>=64 agg

    int tid = threadIdx.x;
    int m0 = blockIdx.x * 32;
    int a  = m0 >> 10;
    int u0 = m0 & 1023;

    // Copy W3 (straight copy, 2048 float4)
#pragma unroll
    for (int i = 0; i < 8; ++i) {
        int lin = tid + i * 256;  // 0..2047
        *(float4*)&sW3[lin * 4] = *(const float4*)&W3[lin * 4];
    }
    // Edge part of X
#pragma unroll
    for (int i = 0; i < 2; ++i) {
        int lin = tid + i * 256;  // 0..511
        int r  = lin >> 4;
        int k4 = (lin & 15) * 4;
        *(float4*)&sX[r * 128 + k4] = *(const float4*)&edge[(size_t)(m0 + r) * DD + k4];
    }
    // Agg part of X
#pragma unroll
    for (int i = 0; i < 2; ++i) {
        int lin = tid + i * 256;  // 0..511
        int r  = lin >> 4;
        int d4 = (lin & 15) * 4;
        int m = m0 + r;
        int u = u0 + r;
        float4 aps = *(const float4*)&g_ap_sum[a * DD + d4];
        float4 ues = *(const float4*)&g_ue_sum[u * DD + d4];
        float4 apr = *(const float4*)&g_ap_res[(size_t)m * DD + d4];
        float4 uer = *(const float4*)&g_ue_res[(size_t)m * DD + d4];
        float4 v;
        v.x = aps.x + ues.x - apr.x - uer.x;
        v.y = aps.y + ues.y - apr.y - uer.y;
        v.z = aps.z + ues.z - apr.z - uer.z;
        v.w = aps.w + ues.w - apr.w - uer.w;
        *(float4*)&sX[r * 128 + 64 + d4] = v;
    }
    __syncthreads();

    int tr = tid >> 4;  // 0..15 -> rows tr*2, tr*2+1
    int tc = tid & 15;  // 0..15 -> cols tc*4..tc*4+3

    float acc[2][4];
#pragma unroll
    for (int i = 0; i < 2; ++i)
#pragma unroll
        for (int j = 0; j < 4; ++j) acc[i][j] = 0.0f;

#pragma unroll 4
    for (int k = 0; k < 128; ++k) {
        float4 bv = *(float4*)&sW3[k * 64 + tc * 4];
        float a0 = sX[(tr * 2 + 0) * 128 + k];
        float a1 = sX[(tr * 2 + 1) * 128 + k];
        acc[0][0] += a0 * bv.x; acc[0][1] += a0 * bv.y;
        acc[0][2] += a0 * bv.z; acc[0][3] += a0 * bv.w;
        acc[1][0] += a1 * bv.x; acc[1][1] += a1 * bv.y;
        acc[1][2] += a1 * bv.z; acc[1][3] += a1 * bv.w;
    }

    float4 bb = *(const float4*)&b3[tc * 4];
#pragma unroll
    for (int i = 0; i < 2; ++i) {
        int m = m0 + tr * 2 + i;
        float4 o;
        o.x = acc[i][0] + bb.x;
        o.y = acc[i][1] + bb.y;
        o.z = acc[i][2] + bb.z;
        o.w = acc[i][3] + bb.w;
        *(float4*)&out[(size_t)m * DD + tc * 4] = o;
    }
}

// ---------------------------------------------------------------------------
extern "C" void kernel_launch(void* const* d_in, const int* in_sizes, int n_in,
                              void* d_out, int out_size) {
    const float* ap_hid = (const float*)d_in[0];
    const float* ue_hid = (const float*)d_in[1];
    const float* edge   = (const float*)d_in[2];
    const float* W1     = (const float*)d_in[3];
    const float* b1     = (const float*)d_in[4];
    const float* W2     = (const float*)d_in[5];
    const float* b2     = (const float*)d_in[6];
    const float* W3     = (const float*)d_in[7];
    const float* b3     = (const float*)d_in[8];
    float* out = (float*)d_out;

    k1_pre<<<NA + NU, 64>>>(ap_hid, ue_hid, W1, b1, W2, b2);
    k2_gemm1<<<NE / 64, 256>>>(edge, W1, W2);
    k3_apsum<<<NA, 256>>>();
    k4_uesum<<<NU, 256>>>();
    k5_gemm2<<<NE / 32, 256>>>(edge, W3, b3, out);
}

// round 6
// speedup vs baseline: 2.0584x; 2.0584x over previous
#include <cuda_runtime.h>
#include <cuda_bf16.h>
#include <cstdint>

#define NA 256
#define NU 1024
#define DD 64
#define NE (NA * NU)

// ---------------- scratch (static __device__, no allocation) ----------------
__device__ __align__(16) float g_ap_sum[NA * DD];
__device__ __align__(16) float g_ue_sum[NU * DD];
__device__ __align__(16) float g_c1[NA * DD];
__device__ __align__(16) float g_c2[NU * DD];
__device__ __align__(16) float g_corr_a[NA * DD];
__device__ __align__(16) float g_corr_u[NU * DD];
// pre-split bf16 weight blobs in ldmatrix-ready swizzled layouts
__device__ __align__(16) unsigned char g_w12h[16384];  // [half][k 0..63][n 0..63]
__device__ __align__(16) unsigned char g_w12l[16384];
__device__ __align__(16) unsigned char g_w3h[16384];   // [k 0..127][n 0..63]
__device__ __align__(16) unsigned char g_w3l[16384];

#define SWZ(x)  ((x) ^ (((x) >> 3) & 0x70))   // 128B-row swizzle
#define SWZO(x) ((x) ^ (((x) >> 4) & 0x70))   // 256B-row swizzle (fp32 out staging)

// smem layout (bytes)
#define OFF_EH   0        // E hi bf16 [128][64]  (aliased by fp32 out staging later)
#define OFF_EL   16384    // E lo
#define OFF_WTH  32768    // W12 hi during MMA1 -> T hi after
#define OFF_WTL  49152
#define OFF_W3H  65536
#define OFF_W3L  81920
#define OFF_C1   98304    // 16*64 f32
#define OFF_C2   102400   // 8*64 f32
#define OFF_UE   104448   // 8*64 f32 partial ue sums
#define SMEM_KT  106496

// ---------------- helpers ----------------
__device__ __forceinline__ uint32_t smem_u32(const void* p) {
    uint32_t a;
    asm("{ .reg .u64 t; cvta.to.shared.u64 t, %1; cvt.u32.u64 %0, t; }" : "=r"(a) : "l"(p));
    return a;
}
__device__ __forceinline__ void ldsm_x4(uint32_t* r, uint32_t addr) {
    asm volatile("ldmatrix.sync.aligned.m8n8.x4.shared.b16 {%0,%1,%2,%3}, [%4];"
                 : "=r"(r[0]), "=r"(r[1]), "=r"(r[2]), "=r"(r[3]) : "r"(addr));
}
__device__ __forceinline__ void ldsm_x2t(uint32_t* r, uint32_t addr) {
    asm volatile("ldmatrix.sync.aligned.m8n8.x2.trans.shared.b16 {%0,%1}, [%2];"
                 : "=r"(r[0]), "=r"(r[1]) : "r"(addr));
}
__device__ __forceinline__ void mma_bf16(float* c, const uint32_t* a, const uint32_t* b) {
    asm volatile("mma.sync.aligned.m16n8k16.row.col.f32.bf16.bf16.f32 "
                 "{%0,%1,%2,%3},{%4,%5,%6,%7},{%8,%9},{%0,%1,%2,%3};"
                 : "+f"(c[0]), "+f"(c[1]), "+f"(c[2]), "+f"(c[3])
                 : "r"(a[0]), "r"(a[1]), "r"(a[2]), "r"(a[3]), "r"(b[0]), "r"(b[1]));
}
__device__ __forceinline__ void bsplit(float x, unsigned short& h, unsigned short& l) {
    __nv_bfloat16 hb = __float2bfloat16(x);
    h = __bfloat16_as_ushort(hb);
    l = __bfloat16_as_ushort(__float2bfloat16(x - __bfloat162float(hb)));
}
__device__ __forceinline__ float frelu(float x) { return fmaxf(x, 0.0f); }

// ---------------------------------------------------------------------------
// K1: c1[a] = b1 + ap_hid[a].W1top ; c2[u] = b2 + ue_hid[u].W2top
// ---------------------------------------------------------------------------
__global__ void k1_pre(const float* __restrict__ ap_hid, const float* __restrict__ ue_hid,
                       const float* __restrict__ W1, const float* __restrict__ b1,
                       const float* __restrict__ W2, const float* __restrict__ b2) {
    __shared__ float sH[DD];
    int bid = blockIdx.x, d = threadIdx.x;
    const float *H, *W, *B; float* out;
    if (bid < NA) { H = ap_hid + bid * DD; W = W1; B = b1; out = g_c1 + bid * DD; }
    else { int u = bid - NA; H = ue_hid + u * DD; W = W2; B = b2; out = g_c2 + u * DD; }
    sH[d] = H[d];
    __syncthreads();
    float acc = B[d];
#pragma unroll 8
    for (int k = 0; k < DD; ++k) acc += sH[k] * W[k * DD + d];
    out[d] = acc;
}

// ---------------------------------------------------------------------------
// K0: build pre-split/swizzled bf16 weight blobs + zero the sums
// grid 128 x 128 = 16384 threads
// ---------------------------------------------------------------------------
__global__ void k0_prep(const float* __restrict__ W1, const float* __restrict__ W2,
                        const float* __restrict__ W3) {
    int id = blockIdx.x * 128 + threadIdx.x;
    if (id < 8192) {                 // W12: [half][k][n], k=bottom rows 64..127
        int h = id >> 12;            // 0=ap(W1), 1=ue(W2)
        int r = id & 4095;
        int k = r >> 6, n = r & 63;
        float f = h ? W2[(64 + k) * DD + n] : W1[(64 + k) * DD + n];
        unsigned short hh, ll; bsplit(f, hh, ll);
        int off = h * 8192 + SWZ(k * 128 + n * 2);
        *(unsigned short*)(g_w12h + off) = hh;
        *(unsigned short*)(g_w12l + off) = ll;
    } else {                          // W3: [k 0..127][n]
        int e = id - 8192;
        int k = e >> 6, n = e & 63;
        float f = W3[k * DD + n];
        unsigned short hh, ll; bsplit(f, hh, ll);
        int off = SWZ(k * 128 + n * 2);
        *(unsigned short*)(g_w3h + off) = hh;
        *(unsigned short*)(g_w3l + off) = ll;
    }
    for (int i = id; i < (NA + NU) * DD; i += 16384) {
        if (i < NA * DD) g_ap_sum[i] = 0.0f;
        else g_ue_sum[i - NA * DD] = 0.0f;
    }
}

// ---------------------------------------------------------------------------
// KT: fused mma.sync kernel. Tile = 16 a x 8 u = 128 edge-rows, 8 warps.
// Warp w owns rows 16w..16w+15 (a = {2w, 2w+1}, u = row&7).
//   MMA1: C[128x128] = E(h/l) . [W1bot|W2bot](h/l)   (3-term split)
//   epi1: ap=relu(c1+Cap), ue=relu(c2+Cue); T=-(ap+ue) -> bf16 h/l smem;
//         ap_sum via shfl-butterfly + REDG; ue_sum via smem partials + REDG
//   MMA2: D[128x64] = [E|T](h/l) . W3(h/l)  -> staged -> coalesced out
// ---------------------------------------------------------------------------
__global__ void __launch_bounds__(256, 2) kt_fused(const float* __restrict__ edge,
                                                   float* __restrict__ out) {
    extern __shared__ char smem[];
    uint32_t sb = smem_u32(smem);
    int t = threadIdx.x, w = t >> 5, lane = t & 31;
    int at = blockIdx.x >> 7, ut = blockIdx.x & 127;
    int a0 = at * 16, u0 = ut * 8;

    // zero ue partials
    ((float*)(smem + OFF_UE))[t] = 0.0f;
    ((float*)(smem + OFF_UE))[t + 256] = 0.0f;
    // c1/c2 slices
#pragma unroll
    for (int i = 0; i < 4; ++i)
        ((float*)(smem + OFF_C1))[i * 256 + t] = g_c1[a0 * DD + i * 256 + t];
    ((float*)(smem + OFF_C2))[t] = g_c2[u0 * DD + t];
    ((float*)(smem + OFF_C2))[t + 256] = g_c2[u0 * DD + t + 256];
    // weight blobs (already swizzled) — straight float4 copies
#pragma unroll
    for (int i = 0; i < 4; ++i) {
        int idx = i * 256 + t;
        ((float4*)(smem + OFF_WTH))[idx] = ((const float4*)g_w12h)[idx];
        ((float4*)(smem + OFF_WTL))[idx] = ((const float4*)g_w12l)[idx];
        ((float4*)(smem + OFF_W3H))[idx] = ((const float4*)g_w3h)[idx];
        ((float4*)(smem + OFF_W3L))[idx] = ((const float4*)g_w3l)[idx];
    }
    // edge tile: fp32 -> bf16 hi/lo, swizzled
#pragma unroll
    for (int i = 0; i < 8; ++i) {
        int lin = i * 256 + t;          // float4 index
        int row = lin >> 4, c4 = lin & 15;
        size_t g = ((size_t)(a0 + (row >> 3)) * NU + (u0 + (row & 7))) * DD + c4 * 4;
        float4 v = *(const float4*)&edge[g];
        unsigned short h0, l0, h1, l1, h2, l2, h3, l3;
        bsplit(v.x, h0, l0); bsplit(v.y, h1, l1);
        bsplit(v.z, h2, l2); bsplit(v.w, h3, l3);
        int so = SWZ(row * 128 + c4 * 8);
        *(uint2*)(smem + OFF_EH + so) =
            make_uint2((uint32_t)h0 | ((uint32_t)h1 << 16), (uint32_t)h2 | ((uint32_t)h3 << 16));
        *(uint2*)(smem + OFF_EL + so) =
            make_uint2((uint32_t)l0 | ((uint32_t)l1 << 16), (uint32_t)l2 | ((uint32_t)l3 << 16));
    }
    __syncthreads();

    int arow = 16 * w + (lane & 15);
    int acol = (lane >> 4) * 16;        // byte col of A k-tile half

    // ---- MMA1 ----
    float acc[16][4];
#pragma unroll
    for (int nt = 0; nt < 16; ++nt)
#pragma unroll
        for (int j = 0; j < 4; ++j) acc[nt][j] = 0.0f;

#pragma unroll
    for (int ks = 0; ks < 4; ++ks) {
        uint32_t ah[4], al[4];
        int ao = SWZ(arow * 128 + ks * 32 + acol);
        ldsm_x4(ah, sb + OFF_EH + ao);
        ldsm_x4(al, sb + OFF_EL + ao);
        int brow = ks * 16 + (lane & 15);
#pragma unroll
        for (int nt = 0; nt < 16; ++nt) {
            uint32_t boff = (uint32_t)((nt >> 3) * 8192 + SWZ(brow * 128 + (nt & 7) * 16));
            uint32_t bh[2], bl[2];
            ldsm_x2t(bh, sb + OFF_WTH + boff);
            ldsm_x2t(bl, sb + OFF_WTL + boff);
            mma_bf16(acc[nt], ah, bh);
            mma_bf16(acc[nt], ah, bl);
            mma_bf16(acc[nt], al, bh);
        }
    }
    __syncthreads();  // W12 fully consumed -> safe to alias as T

    // ---- epilogue 1 ----
    {
        const float* c1s = (const float*)(smem + OFF_C1);
        const float* c2s = (const float*)(smem + OFF_C2);
        float* sue = (float*)(smem + OFF_UE);
        int u_l = lane >> 2, jc = 2 * (lane & 3);
        int aL = 2 * w, aH = 2 * w + 1;
        int r0 = 16 * w + u_l;
#pragma unroll
        for (int nt = 0; nt < 8; ++nt) {
            int col = nt * 8 + jc;
            float vap0 = frelu(c1s[aL * 64 + col]     + acc[nt][0]);
            float vap1 = frelu(c1s[aL * 64 + col + 1] + acc[nt][1]);
            float vap2 = frelu(c1s[aH * 64 + col]     + acc[nt][2]);
            float vap3 = frelu(c1s[aH * 64 + col + 1] + acc[nt][3]);
            float vue0 = frelu(c2s[u_l * 64 + col]     + acc[nt + 8][0]);
            float vue1 = frelu(c2s[u_l * 64 + col + 1] + acc[nt + 8][1]);
            float vue2 = frelu(c2s[u_l * 64 + col]     + acc[nt + 8][2]);
            float vue3 = frelu(c2s[u_l * 64 + col + 1] + acc[nt + 8][3]);
            // T = -(ap+ue), split hi/lo, store (aliases W12 region)
            {
                unsigned short h0, l0, h1, l1;
                bsplit(-(vap0 + vue0), h0, l0); bsplit(-(vap1 + vue1), h1, l1);
                int o = SWZ(r0 * 128 + col * 2);
                *(uint32_t*)(smem + OFF_WTH + o) = (uint32_t)h0 | ((uint32_t)h1 << 16);
                *(uint32_t*)(smem + OFF_WTL + o) = (uint32_t)l0 | ((uint32_t)l1 << 16);
                bsplit(-(vap2 + vue2), h0, l0); bsplit(-(vap3 + vue3), h1, l1);
                o = SWZ((r0 + 8) * 128 + col * 2);
                *(uint32_t*)(smem + OFF_WTH + o) = (uint32_t)h0 | ((uint32_t)h1 << 16);
                *(uint32_t*)(smem + OFF_WTL + o) = (uint32_t)l0 | ((uint32_t)l1 << 16);
            }
            // ue partials into smem (sum over this warp's 2 a's)
            atomicAdd(&sue[u_l * 64 + col],     vue0 + vue2);
            atomicAdd(&sue[u_l * 64 + col + 1], vue1 + vue3);
            // ap sums: butterfly over the 8 u's (lane>>2 axis)
            float s0 = vap0, s1 = vap1, s2 = vap2, s3 = vap3;
#pragma unroll
            for (int d = 4; d < 32; d <<= 1) {
                s0 += __shfl_xor_sync(0xffffffffu, s0, d);
                s1 += __shfl_xor_sync(0xffffffffu, s1, d);
                s2 += __shfl_xor_sync(0xffffffffu, s2, d);
                s3 += __shfl_xor_sync(0xffffffffu, s3, d);
            }
            if (lane < 4) {
                atomicAdd(&g_ap_sum[(a0 + aL) * DD + nt * 8 + 2 * lane],     s0);
                atomicAdd(&g_ap_sum[(a0 + aL) * DD + nt * 8 + 2 * lane + 1], s1);
                atomicAdd(&g_ap_sum[(a0 + aH) * DD + nt * 8 + 2 * lane],     s2);
                atomicAdd(&g_ap_sum[(a0 + aH) * DD + nt * 8 + 2 * lane + 1], s3);
            }
        }
    }
    __syncthreads();  // T complete (cross-lane ldmatrix), sue complete

    // ue cross-block REDs (overlaps MMA2 issue)
    {
        const float* sue = (const float*)(smem + OFF_UE);
#pragma unroll
        for (int i = 0; i < 2; ++i) {
            int idx = t + i * 256;
            atomicAdd(&g_ue_sum[(u0 + (idx >> 6)) * DD + (idx & 63)], sue[idx]);
        }
    }

    // ---- MMA2 ----
    float acc2[8][4];
#pragma unroll
    for (int nt = 0; nt < 8; ++nt)
#pragma unroll
        for (int j = 0; j < 4; ++j) acc2[nt][j] = 0.0f;

#pragma unroll
    for (int ks = 0; ks < 8; ++ks) {
        uint32_t srcH = (ks < 4) ? OFF_EH : OFF_WTH;
        uint32_t srcL = (ks < 4) ? OFF_EL : OFF_WTL;
        uint32_t ah[4], al[4];
        int ao = SWZ(arow * 128 + (ks & 3) * 32 + acol);
        ldsm_x4(ah, sb + srcH + ao);
        ldsm_x4(al, sb + srcL + ao);
        int brow = ks * 16 + (lane & 15);
#pragma unroll
        for (int nt = 0; nt < 8; ++nt) {
            uint32_t boff = (uint32_t)SWZ(brow * 128 + nt * 16);
            uint32_t bh[2], bl[2];
            ldsm_x2t(bh, sb + OFF_W3H + boff);
            ldsm_x2t(bl, sb + OFF_W3L + boff);
            mma_bf16(acc2[nt], ah, bh);
            mma_bf16(acc2[nt], ah, bl);
            mma_bf16(acc2[nt], al, bh);
        }
    }
    __syncthreads();  // E/T consumed -> stage output into OFF_EH region

    // ---- epilogue 2: stage + coalesced write ----
    {
        int u_l = lane >> 2, jc = 2 * (lane & 3);
        int r0 = 16 * w + u_l;
#pragma unroll
        for (int nt = 0; nt < 8; ++nt) {
            int col = nt * 8 + jc;
            *(float2*)(smem + OFF_EH + SWZO(r0 * 256 + col * 4)) =
                make_float2(acc2[nt][0], acc2[nt][1]);
            *(float2*)(smem + OFF_EH + SWZO((r0 + 8) * 256 + col * 4)) =
                make_float2(acc2[nt][2], acc2[nt][3]);
        }
    }
    __syncthreads();
#pragma unroll
    for (int i = 0; i < 8; ++i) {
        int lin = i * 256 + t;
        int row = lin >> 4, c4 = lin & 15;
        float4 v = *(float4*)(smem + OFF_EH + SWZO(row * 256 + c4 * 16));
        size_t g = ((size_t)(a0 + (row >> 3)) * NU + (u0 + (row & 7))) * DD + c4 * 4;
        *(float4*)&out[g] = v;
    }
}

// ---------------------------------------------------------------------------
// KC: corr_a[a] = ap_sum[a].W3bot ; corr_u[u] = ue_sum[u].W3bot   (fp32)
// ---------------------------------------------------------------------------
__global__ void kc_corr(const float* __restrict__ W3) {
    __shared__ float sS[DD];
    int b = blockIdx.x, d = threadIdx.x;
    const float* S; float* O;
    if (b < NA) { S = g_ap_sum + b * DD; O = g_corr_a + b * DD; }
    else { S = g_ue_sum + (b - NA) * DD; O = g_corr_u + (b - NA) * DD; }
    sS[d] = S[d];
    __syncthreads();
    float acc = 0.0f;
#pragma unroll 8
    for (int k = 0; k < DD; ++k) acc += sS[k] * W3[(64 + k) * DD + d];
    O[d] = acc;
}

// ---------------------------------------------------------------------------
// KF: out += corr_a[a] + corr_u[u] + b3
// ---------------------------------------------------------------------------
__global__ void __launch_bounds__(256) kf_final(float* __restrict__ out,
                                                const float* __restrict__ b3) {
    int t0 = blockIdx.x * 256 + threadIdx.x;
#pragma unroll
    for (int i = 0; i < 4; ++i) {
        int fi = t0 + i * 1048576;
        int m = fi >> 4;
        int dq = (fi & 15) * 4;
        int a = m >> 10, u = m & 1023;
        float4 o = ((float4*)out)[fi];
        float4 ca = *(const float4*)&g_corr_a[a * DD + dq];
        float4 cu = *(const float4*)&g_corr_u[u * DD + dq];
        float4 bb = *(const float4*)&b3[dq];
        o.x += ca.x + cu.x + bb.x;
        o.y += ca.y + cu.y + bb.y;
        o.z += ca.z + cu.z + bb.z;
        o.w += ca.w + cu.w + bb.w;
        ((float4*)out)[fi] = o;
    }
}

// ---------------------------------------------------------------------------
extern "C" void kernel_launch(void* const* d_in, const int* in_sizes, int n_in,
                              void* d_out, int out_size) {
    const float* ap_hid = (const float*)d_in[0];
    const float* ue_hid = (const float*)d_in[1];
    const float* edge   = (const float*)d_in[2];
    const float* W1     = (const float*)d_in[3];
    const float* b1     = (const float*)d_in[4];
    const float* W2     = (const float*)d_in[5];
    const float* b2     = (const float*)d_in[6];
    const float* W3     = (const float*)d_in[7];
    const float* b3     = (const float*)d_in[8];
    float* out = (float*)d_out;

    cudaFuncSetAttribute(kt_fused, cudaFuncAttributeMaxDynamicSharedMemorySize, SMEM_KT);

    k1_pre<<<NA + NU, 64>>>(ap_hid, ue_hid, W1, b1, W2, b2);
    k0_prep<<<128, 128>>>(W1, W2, W3);
    kt_fused<<<2048, 256, SMEM_KT>>>(edge, out);
    kc_corr<<<NA + NU, 64>>>(W3);
    kf_final<<<4096, 256>>>(out, b3);
}